// round 7
// baseline (speedup 1.0000x reference)
#include <cuda_runtime.h>
#include <cstdint>

// Shapes fixed by setup_inputs: x [4,2048,4096] f32, W [4096,4096] int8
// (delivered by harness as int32), wscale [4096] f32, bias [4096] f32.
#define D_IN  4096
#define D_OUT 4096
#define MAX_T 8192

// Scratch (allocation-free rule: __device__ globals)
__device__ int8_t g_xq[(size_t)MAX_T * D_IN];
__device__ float  g_xscale[MAX_T];
__device__ int8_t g_wq[(size_t)D_OUT * D_IN];

// ===========================================================================
// Helpers
// ===========================================================================
__device__ __forceinline__ uint32_t smem_u32(const void* p) {
    uint32_t a;
    asm("{ .reg .u64 t; cvta.to.shared.u64 t, %1; cvt.u32.u64 %0, t; }"
        : "=r"(a) : "l"(p));
    return a;
}
#define CP_ASYNC16(dst, src) \
    asm volatile("cp.async.cg.shared.global [%0], [%1], 16;" \
                 :: "r"(dst), "l"(src) : "memory")
#define CP_COMMIT() asm volatile("cp.async.commit_group;" ::: "memory")
#define CP_WAIT(n)  asm volatile("cp.async.wait_group %0;" :: "n"(n) : "memory")
#define CP_WAIT_ALL() asm volatile("cp.async.wait_all;" ::: "memory")
#define BAR_SYNC(id) \
    asm volatile("bar.sync %0, 256;" :: "r"(id) : "memory")

#define LDMATRIX_X4(r0, r1, r2, r3, addr)                                     \
    asm volatile("ldmatrix.sync.aligned.m8n8.x4.shared.b16 {%0,%1,%2,%3}, [%4];" \
                 : "=r"(r0), "=r"(r1), "=r"(r2), "=r"(r3) : "r"(addr))

__device__ __forceinline__ void lds128(int4& v, uint32_t addr) {
    asm volatile("ld.shared.v4.b32 {%0,%1,%2,%3}, [%4];"
                 : "=r"(v.x), "=r"(v.y), "=r"(v.z), "=r"(v.w) : "r"(addr));
}

// int8 tensor-core MMA (sm_80 baseline)
__device__ __forceinline__ void mma_i8(int* c, const uint32_t* a, const uint32_t* b) {
    asm volatile(
        "mma.sync.aligned.m16n8k32.row.col.s32.s8.s8.s32 "
        "{%0,%1,%2,%3}, {%4,%5,%6,%7}, {%8,%9}, {%0,%1,%2,%3};"
        : "+r"(c[0]), "+r"(c[1]), "+r"(c[2]), "+r"(c[3])
        : "r"(a[0]), "r"(a[1]), "r"(a[2]), "r"(a[3]), "r"(b[0]), "r"(b[1]));
}

// ===========================================================================
// Kernel 0: repack weights int32 -> int8
// ===========================================================================
__global__ __launch_bounds__(256) void pack_w_kernel(const int* __restrict__ w32)
{
    const size_t i = (size_t)blockIdx.x * blockDim.x + threadIdx.x;
    const size_t nwords = (size_t)D_OUT * D_IN / 4;
    if (i >= nwords) return;
    const int4 v = reinterpret_cast<const int4*>(w32)[i];
    reinterpret_cast<int*>(g_wq)[i] =
        (v.x & 0xFF) | ((v.y & 0xFF) << 8) | ((v.z & 0xFF) << 16) | ((v.w & 0xFF) << 24);
}

// ===========================================================================
// Kernel 1: dynamic per-token int8 quantization (one CTA / token)
// ===========================================================================
__global__ __launch_bounds__(256) void quant_kernel(const float* __restrict__ x)
{
    const int t = blockIdx.x;
    const float4* __restrict__ xr = reinterpret_cast<const float4*>(x + (size_t)t * D_IN);

    float4 v[4];
    float amax = 0.0f;
#pragma unroll
    for (int i = 0; i < 4; i++) {
        v[i] = xr[threadIdx.x + i * 256];
        amax = fmaxf(amax, fmaxf(fmaxf(fabsf(v[i].x), fabsf(v[i].y)),
                                 fmaxf(fabsf(v[i].z), fabsf(v[i].w))));
    }
    __shared__ float red[8];
#pragma unroll
    for (int o = 16; o > 0; o >>= 1)
        amax = fmaxf(amax, __shfl_xor_sync(0xffffffffu, amax, o));
    if ((threadIdx.x & 31) == 0) red[threadIdx.x >> 5] = amax;
    __syncthreads();
    float m = red[0];
#pragma unroll
    for (int w = 1; w < 8; w++) m = fmaxf(m, red[w]);

    const float scale = fmaxf(m, 1e-8f) / 127.0f;
    if (threadIdx.x == 0) g_xscale[t] = scale;

    int* __restrict__ outw = reinterpret_cast<int*>(g_xq + (size_t)t * D_IN);
#pragma unroll
    for (int i = 0; i < 4; i++) {
        int q0 = (int)fminf(fmaxf(rintf(v[i].x / scale), -128.0f), 127.0f);
        int q1 = (int)fminf(fmaxf(rintf(v[i].y / scale), -128.0f), 127.0f);
        int q2 = (int)fminf(fmaxf(rintf(v[i].z / scale), -128.0f), 127.0f);
        int q3 = (int)fminf(fmaxf(rintf(v[i].w / scale), -128.0f), 127.0f);
        outw[threadIdx.x + i * 256] = (q0 & 0xFF) | ((q1 & 0xFF) << 8) |
                                      ((q2 & 0xFF) << 16) | ((q3 & 0xFF) << 24);
    }
}

// ===========================================================================
// Kernel 2: HYBRID int8 GEMM — tensor pipe (mma.sync) + ALU pipe (dp4a),
// now FULLY DECOUPLED: each path has its own A tile, its own cp.async
// groups, and its own named barrier (bar.sync 1 / bar.sync 2, 256 threads),
// so the faster path never waits for the straggler inside the K loop.
// CTA tile 128x256: warps 0-7 -> cols [0,128) mma.sync; warps 8-15 ->
// cols [128,256) dp4a. One __syncthreads at the (convergent) epilogue.
// ===========================================================================
#define BM 128
#define BN_T 128
#define BN_D 128
#define BN (BN_T + BN_D)
#define BK 64
#define STAGES 3
#define NKB (D_IN / BK)          // 64
#define ROW_B 80                 // padded row stride (tensor tiles)
#define A_TILE (BM * ROW_B)      // 10240
#define BT_TILE (BN_T * ROW_B)   // 10240
#define STAGE_T (A_TILE + BT_TILE)           // 20480
#define OFF_D (STAGES * STAGE_T)             // 61440
#define A2_TILE (4 * BM * 16)                // 8192 ([kw4][row] int4)
#define B2_TILE (4 * BN_D * 16)              // 8192 ([kw4][col] int4)
#define STAGE_D (A2_TILE + B2_TILE)          // 16384
#define SMEM_TOTAL (OFF_D + STAGES * STAGE_D)    // 110592

__global__ __launch_bounds__(512, 1) void gemm_hybrid_kernel(
    const float* __restrict__ wscale,
    const float* __restrict__ bias,
    float* __restrict__ out)
{
    extern __shared__ char smem[];
    const uint32_t sbase = smem_u32(smem);

    const int tid  = threadIdx.x;
    const int lane = tid & 31;
    const int wid  = tid >> 5;

    const int m0 = blockIdx.y * BM;
    const int n0 = blockIdx.x * BN;

    // state carried into the convergent epilogue
    int acc_t[2][8][4];   // tensor accumulators
    int acc_d[8][8];      // dp4a accumulators

    if (wid < 8) {
        // ===============================================================
        // TENSOR PATH (warps 0-7): cols [n0, n0+128), mma.sync m16n8k32
        // ===============================================================
        const int wm = wid & 3;
        const int wn = wid >> 2;

        const int ldrow = tid >> 2;      // 0..63
        const int ldc   = tid & 3;       // 0..3

#pragma unroll
        for (int mt = 0; mt < 2; mt++)
#pragma unroll
            for (int nt = 0; nt < 8; nt++)
#pragma unroll
                for (int r = 0; r < 4; r++) acc_t[mt][nt][r] = 0;

        auto load_stage = [&](int s, int kb) {
            const uint32_t sa = sbase + s * STAGE_T;
            const uint32_t sb = sa + A_TILE;
            const size_t kcol = (size_t)kb * BK + ldc * 16;
#pragma unroll
            for (int h = 0; h < 2; h++) {
                const int row = ldrow + h * 64;
                CP_ASYNC16(sa + row * ROW_B + ldc * 16,
                           g_xq + (size_t)(m0 + row) * D_IN + kcol);
            }
#pragma unroll
            for (int h = 0; h < 2; h++) {
                const int row = ldrow + h * 64;
                CP_ASYNC16(sb + row * ROW_B + ldc * 16,
                           g_wq + (size_t)(n0 + row) * D_IN + kcol);
            }
        };

#pragma unroll
        for (int s = 0; s < STAGES - 1; s++) {
            load_stage(s, s);
            CP_COMMIT();
        }

        const int a_row = wm * 32 + (lane & 7) + ((lane >> 3) & 1) * 8;
        const int a_b16 = (lane >> 4) * 16;
        uint32_t a_lo[2][2];
#pragma unroll
        for (int mt = 0; mt < 2; mt++)
#pragma unroll
            for (int ks = 0; ks < 2; ks++)
                a_lo[mt][ks] = (uint32_t)((a_row + mt * 16) * ROW_B + ks * 32 + a_b16);

        const int b_row = wn * 64 + (lane & 7) + ((lane >> 4) & 1) * 8;
        const int b_b16 = ((lane >> 3) & 1) * 16;
        uint32_t b_lo[4][2];
#pragma unroll
        for (int t = 0; t < 4; t++)
#pragma unroll
            for (int ks = 0; ks < 2; ks++)
                b_lo[t][ks] = (uint32_t)(A_TILE + (b_row + t * 16) * ROW_B + ks * 32 + b_b16);

#pragma unroll 1
        for (int kb = 0; kb < NKB; kb++) {
            CP_WAIT(STAGES - 2);
            BAR_SYNC(1);    // tensor warps only

            const int pf = kb + STAGES - 1;
            if (pf < NKB) load_stage(pf % STAGES, pf);
            CP_COMMIT();

            const uint32_t st = sbase + (kb % STAGES) * STAGE_T;
#pragma unroll
            for (int ks = 0; ks < 2; ks++) {
                uint32_t af[2][4], bf[8][2];
#pragma unroll
                for (int mt = 0; mt < 2; mt++)
                    LDMATRIX_X4(af[mt][0], af[mt][1], af[mt][2], af[mt][3],
                                st + a_lo[mt][ks]);
#pragma unroll
                for (int t = 0; t < 4; t++)
                    LDMATRIX_X4(bf[2 * t][0], bf[2 * t][1], bf[2 * t + 1][0],
                                bf[2 * t + 1][1], st + b_lo[t][ks]);
#pragma unroll
                for (int mt = 0; mt < 2; mt++)
#pragma unroll
                    for (int nt = 0; nt < 8; nt++)
                        mma_i8(acc_t[mt][nt], af[mt], bf[nt]);
            }
        }

        CP_WAIT_ALL();
        BAR_SYNC(1);        // all tensor warps done reading stage 0 region
        // stage wscale/bias for the whole CTA (overlays tensor stage 0)
        {
            float* ws_s = reinterpret_cast<float*>(smem);
            float* bs_s = ws_s + BN;
            if (tid < BN) {
                ws_s[tid] = wscale[n0 + tid];
                bs_s[tid] = bias[n0 + tid];
            }
        }
    } else {
        // ===============================================================
        // DP4A PATH (warps 8-15): cols [n0+128, n0+256), own A2 copy.
        // A2/B2: [kw4][row] int4 — conflict-free LDS.128 / broadcast.
        // ===============================================================
        const int t2 = tid - 256;         // 0..255
        const int tx = t2 & 15;           // col group
        const int ty = t2 >> 4;           // row group 0..15

#pragma unroll
        for (int i = 0; i < 8; i++)
#pragma unroll
            for (int j = 0; j < 8; j++) acc_d[i][j] = 0;

        auto load_stage_d = [&](int s, int kb) {
            const uint32_t sd = sbase + OFF_D + s * STAGE_D;
            const size_t kcol = (size_t)kb * BK;
#pragma unroll
            for (int c = 0; c < 4; c++) {
                const int idx = t2 + c * 256;      // 0..1023
                if (idx < 512) {                    // A2
                    const int row = idx >> 2, kw4 = idx & 3;
                    CP_ASYNC16(sd + (kw4 * BM + row) * 16,
                               g_xq + (size_t)(m0 + row) * D_IN + kcol + kw4 * 16);
                } else {                            // B2
                    const int i2 = idx - 512;
                    const int col = i2 >> 2, kw4 = i2 & 3;
                    CP_ASYNC16(sd + A2_TILE + (kw4 * BN_D + col) * 16,
                               g_wq + (size_t)(n0 + BN_T + col) * D_IN + kcol + kw4 * 16);
                }
            }
        };

#pragma unroll
        for (int s = 0; s < STAGES - 1; s++) {
            load_stage_d(s, s);
            CP_COMMIT();
        }

#pragma unroll 1
        for (int kb = 0; kb < NKB; kb++) {
            CP_WAIT(STAGES - 2);
            BAR_SYNC(2);    // dp4a warps only

            const int pf = kb + STAGES - 1;
            if (pf < NKB) load_stage_d(pf % STAGES, pf);
            CP_COMMIT();

            const uint32_t sd = sbase + OFF_D + (kb % STAGES) * STAGE_D;

#pragma unroll
            for (int kw4 = 0; kw4 < 4; kw4++) {
                int4 b[8];
#pragma unroll
                for (int j = 0; j < 8; j++)
                    lds128(b[j], sd + A2_TILE + (kw4 * BN_D + j * 16 + tx) * 16);
#pragma unroll
                for (int i = 0; i < 8; i++) {
                    int4 a;
                    lds128(a, sd + (kw4 * BM + ty * 8 + i) * 16);
#pragma unroll
                    for (int j = 0; j < 8; j++) {
                        acc_d[i][j] = __dp4a(a.x, b[j].x, acc_d[i][j]);
                        acc_d[i][j] = __dp4a(a.y, b[j].y, acc_d[i][j]);
                        acc_d[i][j] = __dp4a(a.z, b[j].z, acc_d[i][j]);
                        acc_d[i][j] = __dp4a(a.w, b[j].w, acc_d[i][j]);
                    }
                }
            }
        }
        CP_WAIT_ALL();
    }

    // ---- convergent point: ws/bs visible to everyone after this ----
    __syncthreads();

    const float* ws_s = reinterpret_cast<const float*>(smem);
    const float* bs_s = ws_s + BN;

    if (wid < 8) {
        // tensor epilogue
        const int g  = lane >> 2;
        const int tq = lane & 3;
        const int wm = wid & 3;
        const int wn = wid >> 2;
#pragma unroll
        for (int mt = 0; mt < 2; mt++) {
            const int row0 = m0 + wm * 32 + mt * 16 + g;
            const float xs0 = g_xscale[row0];
            const float xs1 = g_xscale[row0 + 8];
            float* __restrict__ o0 = out + (size_t)row0 * D_OUT;
            float* __restrict__ o1 = out + (size_t)(row0 + 8) * D_OUT;
#pragma unroll
            for (int nt = 0; nt < 8; nt++) {
                const int nl = wn * 64 + nt * 8 + tq * 2;
                const float w0 = ws_s[nl], w1 = ws_s[nl + 1];
                const float b0 = bs_s[nl], b1 = bs_s[nl + 1];
                float2 v0, v1;
                v0.x = (float)acc_t[mt][nt][0] * xs0 * w0 + b0;
                v0.y = (float)acc_t[mt][nt][1] * xs0 * w1 + b1;
                v1.x = (float)acc_t[mt][nt][2] * xs1 * w0 + b0;
                v1.y = (float)acc_t[mt][nt][3] * xs1 * w1 + b1;
                *reinterpret_cast<float2*>(o0 + n0 + nl) = v0;
                *reinterpret_cast<float2*>(o1 + n0 + nl) = v1;
            }
        }
    } else {
        // dp4a epilogue
        const int t2 = tid - 256;
        const int tx = t2 & 15;
        const int ty = t2 >> 4;
#pragma unroll
        for (int i = 0; i < 8; i++) {
            const int m = m0 + ty * 8 + i;
            const float xs = g_xscale[m];
            float* __restrict__ orow = out + (size_t)m * D_OUT;
#pragma unroll
            for (int j = 0; j < 8; j++) {
                const int nl = BN_T + j * 16 + tx;
                orow[n0 + nl] = (float)acc_d[i][j] * xs * ws_s[nl] + bs_s[nl];
            }
        }
    }
}

// ===========================================================================
extern "C" void kernel_launch(void* const* d_in, const int* in_sizes, int n_in,
                              void* d_out, int out_size)
{
    const float* x      = (const float*)d_in[0];
    const int*   w32    = (const int*)d_in[1];
    const float* wscale = (const float*)d_in[2];
    const float* bias   = (const float*)d_in[3];
    float*       out    = (float*)d_out;

    const int T = in_sizes[0] / D_IN;   // 8192

    const size_t nwords = (size_t)D_OUT * D_IN / 4;
    pack_w_kernel<<<(int)((nwords + 255) / 256), 256>>>(w32);
    quant_kernel<<<T, 256>>>(x);

    static bool attr_set = false;
    if (!attr_set) {
        cudaFuncSetAttribute(gemm_hybrid_kernel,
                             cudaFuncAttributeMaxDynamicSharedMemorySize, SMEM_TOTAL);
        attr_set = true;
    }
    dim3 grid(D_OUT / BN, T / BM);      // (16, 64)
    gemm_hybrid_kernel<<<grid, 512, SMEM_TOTAL>>>(wscale, bias, out);
}

// round 8
// speedup vs baseline: 1.0575x; 1.0575x over previous
#include <cuda_runtime.h>
#include <cstdint>

// Shapes fixed by setup_inputs: x [4,2048,4096] f32, W [4096,4096] int8
// (delivered by harness as int32), wscale [4096] f32, bias [4096] f32.
#define D_IN  4096
#define D_OUT 4096
#define MAX_T 8192

// Scratch (allocation-free rule: __device__ globals)
__device__ int8_t g_xq[(size_t)MAX_T * D_IN];
__device__ float  g_xscale[MAX_T];
__device__ int8_t g_wq[(size_t)D_OUT * D_IN];

// ===========================================================================
// Helpers
// ===========================================================================
__device__ __forceinline__ uint32_t smem_u32(const void* p) {
    uint32_t a;
    asm("{ .reg .u64 t; cvta.to.shared.u64 t, %1; cvt.u32.u64 %0, t; }"
        : "=r"(a) : "l"(p));
    return a;
}
#define CP_ASYNC16(dst, src) \
    asm volatile("cp.async.cg.shared.global [%0], [%1], 16;" \
                 :: "r"(dst), "l"(src) : "memory")
#define CP_COMMIT() asm volatile("cp.async.commit_group;" ::: "memory")
#define CP_WAIT(n)  asm volatile("cp.async.wait_group %0;" :: "n"(n) : "memory")
#define BAR_SYNC(id) \
    asm volatile("bar.sync %0, 256;" :: "r"(id) : "memory")

#define LDMATRIX_X4(r0, r1, r2, r3, addr)                                     \
    asm volatile("ldmatrix.sync.aligned.m8n8.x4.shared.b16 {%0,%1,%2,%3}, [%4];" \
                 : "=r"(r0), "=r"(r1), "=r"(r2), "=r"(r3) : "r"(addr))

__device__ __forceinline__ void lds128(int4& v, uint32_t addr) {
    asm volatile("ld.shared.v4.b32 {%0,%1,%2,%3}, [%4];"
                 : "=r"(v.x), "=r"(v.y), "=r"(v.z), "=r"(v.w) : "r"(addr));
}

// int8 tensor-core MMA (sm_80 baseline)
__device__ __forceinline__ void mma_i8(int* c, const uint32_t* a, const uint32_t* b) {
    asm volatile(
        "mma.sync.aligned.m16n8k32.row.col.s32.s8.s8.s32 "
        "{%0,%1,%2,%3}, {%4,%5,%6,%7}, {%8,%9}, {%0,%1,%2,%3};"
        : "+r"(c[0]), "+r"(c[1]), "+r"(c[2]), "+r"(c[3])
        : "r"(a[0]), "r"(a[1]), "r"(a[2]), "r"(a[3]), "r"(b[0]), "r"(b[1]));
}

// ===========================================================================
// Kernel 0: repack weights int32 -> int8
// ===========================================================================
__global__ __launch_bounds__(256) void pack_w_kernel(const int* __restrict__ w32)
{
    const size_t i = (size_t)blockIdx.x * blockDim.x + threadIdx.x;
    const size_t nwords = (size_t)D_OUT * D_IN / 4;
    if (i >= nwords) return;
    const int4 v = reinterpret_cast<const int4*>(w32)[i];
    reinterpret_cast<int*>(g_wq)[i] =
        (v.x & 0xFF) | ((v.y & 0xFF) << 8) | ((v.z & 0xFF) << 16) | ((v.w & 0xFF) << 24);
}

// ===========================================================================
// Kernel 1: dynamic per-token int8 quantization (one CTA / token)
// ===========================================================================
__global__ __launch_bounds__(256) void quant_kernel(const float* __restrict__ x)
{
    const int t = blockIdx.x;
    const float4* __restrict__ xr = reinterpret_cast<const float4*>(x + (size_t)t * D_IN);

    float4 v[4];
    float amax = 0.0f;
#pragma unroll
    for (int i = 0; i < 4; i++) {
        v[i] = xr[threadIdx.x + i * 256];
        amax = fmaxf(amax, fmaxf(fmaxf(fabsf(v[i].x), fabsf(v[i].y)),
                                 fmaxf(fabsf(v[i].z), fabsf(v[i].w))));
    }
    __shared__ float red[8];
#pragma unroll
    for (int o = 16; o > 0; o >>= 1)
        amax = fmaxf(amax, __shfl_xor_sync(0xffffffffu, amax, o));
    if ((threadIdx.x & 31) == 0) red[threadIdx.x >> 5] = amax;
    __syncthreads();
    float m = red[0];
#pragma unroll
    for (int w = 1; w < 8; w++) m = fmaxf(m, red[w]);

    const float scale = fmaxf(m, 1e-8f) / 127.0f;
    if (threadIdx.x == 0) g_xscale[t] = scale;

    int* __restrict__ outw = reinterpret_cast<int*>(g_xq + (size_t)t * D_IN);
#pragma unroll
    for (int i = 0; i < 4; i++) {
        int q0 = (int)fminf(fmaxf(rintf(v[i].x / scale), -128.0f), 127.0f);
        int q1 = (int)fminf(fmaxf(rintf(v[i].y / scale), -128.0f), 127.0f);
        int q2 = (int)fminf(fmaxf(rintf(v[i].z / scale), -128.0f), 127.0f);
        int q3 = (int)fminf(fmaxf(rintf(v[i].w / scale), -128.0f), 127.0f);
        outw[threadIdx.x + i * 256] = (q0 & 0xFF) | ((q1 & 0xFF) << 8) |
                                      ((q2 & 0xFF) << 16) | ((q3 & 0xFF) << 24);
    }
}

// ===========================================================================
// Kernel 2: HYBRID int8 GEMM — tensor pipe (mma.sync) + ALU pipe (dp4a),
// decoupled via per-path named barriers (bar.sync 1 / 2, 256 threads), with
// accumulators + epilogue kept INSIDE each branch (no function-scope live
// ranges across a convergent sync -> no register spills; R7's regression).
// Epilogues read wscale/bias via __ldg (L2-hot), so there is NO cross-path
// synchronization anywhere. CTA tile 128x256, 3-stage cp.async pipelines.
// ===========================================================================
#define BM 128
#define BN_T 128
#define BN_D 128
#define BN (BN_T + BN_D)
#define BK 64
#define STAGES 3
#define NKB (D_IN / BK)          // 64
#define ROW_B 80                 // padded row stride (tensor tiles)
#define A_TILE (BM * ROW_B)      // 10240
#define BT_TILE (BN_T * ROW_B)   // 10240
#define STAGE_T (A_TILE + BT_TILE)           // 20480
#define OFF_D (STAGES * STAGE_T)             // 61440
#define A2_TILE (4 * BM * 16)                // 8192 ([kw4][row] int4)
#define B2_TILE (4 * BN_D * 16)              // 8192 ([kw4][col] int4)
#define STAGE_D (A2_TILE + B2_TILE)          // 16384
#define SMEM_TOTAL (OFF_D + STAGES * STAGE_D)    // 110592

__global__ __launch_bounds__(512, 1) void gemm_hybrid_kernel(
    const float* __restrict__ wscale,
    const float* __restrict__ bias,
    float* __restrict__ out)
{
    extern __shared__ char smem[];
    const uint32_t sbase = smem_u32(smem);

    const int tid  = threadIdx.x;
    const int lane = tid & 31;
    const int wid  = tid >> 5;

    const int m0 = blockIdx.y * BM;
    const int n0 = blockIdx.x * BN;

    if (wid < 8) {
        // ===============================================================
        // TENSOR PATH (warps 0-7): cols [n0, n0+128), mma.sync m16n8k32
        // ===============================================================
        const int g  = lane >> 2;
        const int tq = lane & 3;
        const int wm = wid & 3;
        const int wn = wid >> 2;

        const int ldrow = tid >> 2;      // 0..63
        const int ldc   = tid & 3;       // 0..3

        int acc[2][8][4];
#pragma unroll
        for (int mt = 0; mt < 2; mt++)
#pragma unroll
            for (int nt = 0; nt < 8; nt++)
#pragma unroll
                for (int r = 0; r < 4; r++) acc[mt][nt][r] = 0;

        auto load_stage = [&](int s, int kb) {
            const uint32_t sa = sbase + s * STAGE_T;
            const uint32_t sb = sa + A_TILE;
            const size_t kcol = (size_t)kb * BK + ldc * 16;
#pragma unroll
            for (int h = 0; h < 2; h++) {
                const int row = ldrow + h * 64;
                CP_ASYNC16(sa + row * ROW_B + ldc * 16,
                           g_xq + (size_t)(m0 + row) * D_IN + kcol);
            }
#pragma unroll
            for (int h = 0; h < 2; h++) {
                const int row = ldrow + h * 64;
                CP_ASYNC16(sb + row * ROW_B + ldc * 16,
                           g_wq + (size_t)(n0 + row) * D_IN + kcol);
            }
        };

#pragma unroll
        for (int s = 0; s < STAGES - 1; s++) {
            load_stage(s, s);
            CP_COMMIT();
        }

        const int a_row = wm * 32 + (lane & 7) + ((lane >> 3) & 1) * 8;
        const int a_b16 = (lane >> 4) * 16;
        uint32_t a_lo[2][2];
#pragma unroll
        for (int mt = 0; mt < 2; mt++)
#pragma unroll
            for (int ks = 0; ks < 2; ks++)
                a_lo[mt][ks] = (uint32_t)((a_row + mt * 16) * ROW_B + ks * 32 + a_b16);

        const int b_row = wn * 64 + (lane & 7) + ((lane >> 4) & 1) * 8;
        const int b_b16 = ((lane >> 3) & 1) * 16;
        uint32_t b_lo[4][2];
#pragma unroll
        for (int t = 0; t < 4; t++)
#pragma unroll
            for (int ks = 0; ks < 2; ks++)
                b_lo[t][ks] = (uint32_t)(A_TILE + (b_row + t * 16) * ROW_B + ks * 32 + b_b16);

#pragma unroll 1
        for (int kb = 0; kb < NKB; kb++) {
            CP_WAIT(STAGES - 2);
            BAR_SYNC(1);    // tensor warps only

            const int pf = kb + STAGES - 1;
            if (pf < NKB) load_stage(pf % STAGES, pf);
            CP_COMMIT();

            const uint32_t st = sbase + (kb % STAGES) * STAGE_T;
#pragma unroll
            for (int ks = 0; ks < 2; ks++) {
                uint32_t af[2][4], bf[8][2];
#pragma unroll
                for (int mt = 0; mt < 2; mt++)
                    LDMATRIX_X4(af[mt][0], af[mt][1], af[mt][2], af[mt][3],
                                st + a_lo[mt][ks]);
#pragma unroll
                for (int t = 0; t < 4; t++)
                    LDMATRIX_X4(bf[2 * t][0], bf[2 * t][1], bf[2 * t + 1][0],
                                bf[2 * t + 1][1], st + b_lo[t][ks]);
#pragma unroll
                for (int mt = 0; mt < 2; mt++)
#pragma unroll
                    for (int nt = 0; nt < 8; nt++)
                        mma_i8(acc[mt][nt], af[mt], bf[nt]);
            }
        }

        // ---- tensor epilogue (scales/bias via __ldg, no smem, no sync) ----
#pragma unroll
        for (int mt = 0; mt < 2; mt++) {
            const int row0 = m0 + wm * 32 + mt * 16 + g;
            const float xs0 = g_xscale[row0];
            const float xs1 = g_xscale[row0 + 8];
            float* __restrict__ o0 = out + (size_t)row0 * D_OUT;
            float* __restrict__ o1 = out + (size_t)(row0 + 8) * D_OUT;
#pragma unroll
            for (int nt = 0; nt < 8; nt++) {
                const int n = n0 + wn * 64 + nt * 8 + tq * 2;
                const float w0 = __ldg(wscale + n), w1 = __ldg(wscale + n + 1);
                const float b0 = __ldg(bias + n),   b1 = __ldg(bias + n + 1);
                float2 v0, v1;
                v0.x = (float)acc[mt][nt][0] * xs0 * w0 + b0;
                v0.y = (float)acc[mt][nt][1] * xs0 * w1 + b1;
                v1.x = (float)acc[mt][nt][2] * xs1 * w0 + b0;
                v1.y = (float)acc[mt][nt][3] * xs1 * w1 + b1;
                *reinterpret_cast<float2*>(o0 + n) = v0;
                *reinterpret_cast<float2*>(o1 + n) = v1;
            }
        }
    } else {
        // ===============================================================
        // DP4A PATH (warps 8-15): cols [n0+128, n0+256), own A2 copy.
        // A2/B2: [kw4][row] int4 — conflict-free LDS.128 / broadcast.
        // ===============================================================
        const int t2 = tid - 256;         // 0..255
        const int tx = t2 & 15;           // col group
        const int ty = t2 >> 4;           // row group 0..15

        int acc[8][8];
#pragma unroll
        for (int i = 0; i < 8; i++)
#pragma unroll
            for (int j = 0; j < 8; j++) acc[i][j] = 0;

        auto load_stage_d = [&](int s, int kb) {
            const uint32_t sd = sbase + OFF_D + s * STAGE_D;
            const size_t kcol = (size_t)kb * BK;
#pragma unroll
            for (int c = 0; c < 4; c++) {
                const int idx = t2 + c * 256;      // 0..1023
                if (idx < 512) {                    // A2
                    const int row = idx >> 2, kw4 = idx & 3;
                    CP_ASYNC16(sd + (kw4 * BM + row) * 16,
                               g_xq + (size_t)(m0 + row) * D_IN + kcol + kw4 * 16);
                } else {                            // B2
                    const int i2 = idx - 512;
                    const int col = i2 >> 2, kw4 = i2 & 3;
                    CP_ASYNC16(sd + A2_TILE + (kw4 * BN_D + col) * 16,
                               g_wq + (size_t)(n0 + BN_T + col) * D_IN + kcol + kw4 * 16);
                }
            }
        };

#pragma unroll
        for (int s = 0; s < STAGES - 1; s++) {
            load_stage_d(s, s);
            CP_COMMIT();
        }

#pragma unroll 1
        for (int kb = 0; kb < NKB; kb++) {
            CP_WAIT(STAGES - 2);
            BAR_SYNC(2);    // dp4a warps only

            const int pf = kb + STAGES - 1;
            if (pf < NKB) load_stage_d(pf % STAGES, pf);
            CP_COMMIT();

            const uint32_t sd = sbase + OFF_D + (kb % STAGES) * STAGE_D;

#pragma unroll
            for (int kw4 = 0; kw4 < 4; kw4++) {
                int4 b[8];
#pragma unroll
                for (int j = 0; j < 8; j++)
                    lds128(b[j], sd + A2_TILE + (kw4 * BN_D + j * 16 + tx) * 16);
#pragma unroll
                for (int i = 0; i < 8; i++) {
                    int4 a;
                    lds128(a, sd + (kw4 * BM + ty * 8 + i) * 16);
#pragma unroll
                    for (int j = 0; j < 8; j++) {
                        acc[i][j] = __dp4a(a.x, b[j].x, acc[i][j]);
                        acc[i][j] = __dp4a(a.y, b[j].y, acc[i][j]);
                        acc[i][j] = __dp4a(a.z, b[j].z, acc[i][j]);
                        acc[i][j] = __dp4a(a.w, b[j].w, acc[i][j]);
                    }
                }
            }
        }

        // ---- dp4a epilogue (scales/bias via __ldg, no smem, no sync) ----
#pragma unroll
        for (int i = 0; i < 8; i++) {
            const int m = m0 + ty * 8 + i;
            const float xs = g_xscale[m];
            float* __restrict__ orow = out + (size_t)m * D_OUT;
#pragma unroll
            for (int j = 0; j < 8; j++) {
                const int n = n0 + BN_T + j * 16 + tx;
                orow[n] = (float)acc[i][j] * xs * __ldg(wscale + n) + __ldg(bias + n);
            }
        }
    }
}

// ===========================================================================
extern "C" void kernel_launch(void* const* d_in, const int* in_sizes, int n_in,
                              void* d_out, int out_size)
{
    const float* x      = (const float*)d_in[0];
    const int*   w32    = (const int*)d_in[1];
    const float* wscale = (const float*)d_in[2];
    const float* bias   = (const float*)d_in[3];
    float*       out    = (float*)d_out;

    const int T = in_sizes[0] / D_IN;   // 8192

    const size_t nwords = (size_t)D_OUT * D_IN / 4;
    pack_w_kernel<<<(int)((nwords + 255) / 256), 256>>>(w32);
    quant_kernel<<<T, 256>>>(x);

    static bool attr_set = false;
    if (!attr_set) {
        cudaFuncSetAttribute(gemm_hybrid_kernel,
                             cudaFuncAttributeMaxDynamicSharedMemorySize, SMEM_TOTAL);
        attr_set = true;
    }
    dim3 grid(D_OUT / BN, T / BM);      // (16, 64)
    gemm_hybrid_kernel<<<grid, 512, SMEM_TOTAL>>>(wscale, bias, out);
}

// round 9
// speedup vs baseline: 1.1146x; 1.0539x over previous
#include <cuda_runtime.h>
#include <cstdint>

// Shapes fixed by setup_inputs: x [4,2048,4096] f32, W [4096,4096] int8
// (delivered by harness as int32), wscale [4096] f32, bias [4096] f32.
#define D_IN  4096
#define D_OUT 4096
#define MAX_T 8192

// Scratch (allocation-free rule: __device__ globals)
__device__ int8_t g_xq[(size_t)MAX_T * D_IN];
__device__ float  g_xscale[MAX_T];
__device__ int8_t g_wq[(size_t)D_OUT * D_IN];

// ===========================================================================
// Helpers
// ===========================================================================
__device__ __forceinline__ uint32_t smem_u32(const void* p) {
    uint32_t a;
    asm("{ .reg .u64 t; cvta.to.shared.u64 t, %1; cvt.u32.u64 %0, t; }"
        : "=r"(a) : "l"(p));
    return a;
}
#define CP_ASYNC16(dst, src) \
    asm volatile("cp.async.cg.shared.global [%0], [%1], 16;" \
                 :: "r"(dst), "l"(src) : "memory")
#define CP_COMMIT() asm volatile("cp.async.commit_group;" ::: "memory")
#define CP_WAIT(n)  asm volatile("cp.async.wait_group %0;" :: "n"(n) : "memory")
#define CP_WAIT_ALL() asm volatile("cp.async.wait_all;" ::: "memory")

#define LDMATRIX_X4(r0, r1, r2, r3, addr)                                     \
    asm volatile("ldmatrix.sync.aligned.m8n8.x4.shared.b16 {%0,%1,%2,%3}, [%4];" \
                 : "=r"(r0), "=r"(r1), "=r"(r2), "=r"(r3) : "r"(addr))
#define LDMATRIX_X2(r0, r1, addr)                                             \
    asm volatile("ldmatrix.sync.aligned.m8n8.x2.shared.b16 {%0,%1}, [%2];"    \
                 : "=r"(r0), "=r"(r1) : "r"(addr))

__device__ __forceinline__ void lds128(int4& v, uint32_t addr) {
    asm volatile("ld.shared.v4.b32 {%0,%1,%2,%3}, [%4];"
                 : "=r"(v.x), "=r"(v.y), "=r"(v.z), "=r"(v.w) : "r"(addr));
}

// int8 tensor-core MMA (sm_80 baseline)
__device__ __forceinline__ void mma_i8(int* c, const uint32_t* a, const uint32_t* b) {
    asm volatile(
        "mma.sync.aligned.m16n8k32.row.col.s32.s8.s8.s32 "
        "{%0,%1,%2,%3}, {%4,%5,%6,%7}, {%8,%9}, {%0,%1,%2,%3};"
        : "+r"(c[0]), "+r"(c[1]), "+r"(c[2]), "+r"(c[3])
        : "r"(a[0]), "r"(a[1]), "r"(a[2]), "r"(a[3]), "r"(b[0]), "r"(b[1]));
}

// ===========================================================================
// Kernel 0: repack weights int32 -> int8
// ===========================================================================
__global__ __launch_bounds__(256) void pack_w_kernel(const int* __restrict__ w32)
{
    const size_t i = (size_t)blockIdx.x * blockDim.x + threadIdx.x;
    const size_t nwords = (size_t)D_OUT * D_IN / 4;
    if (i >= nwords) return;
    const int4 v = reinterpret_cast<const int4*>(w32)[i];
    reinterpret_cast<int*>(g_wq)[i] =
        (v.x & 0xFF) | ((v.y & 0xFF) << 8) | ((v.z & 0xFF) << 16) | ((v.w & 0xFF) << 24);
}

// ===========================================================================
// Kernel 1: dynamic per-token int8 quantization (one CTA / token)
// ===========================================================================
__global__ __launch_bounds__(256) void quant_kernel(const float* __restrict__ x)
{
    const int t = blockIdx.x;
    const float4* __restrict__ xr = reinterpret_cast<const float4*>(x + (size_t)t * D_IN);

    float4 v[4];
    float amax = 0.0f;
#pragma unroll
    for (int i = 0; i < 4; i++) {
        v[i] = xr[threadIdx.x + i * 256];
        amax = fmaxf(amax, fmaxf(fmaxf(fabsf(v[i].x), fabsf(v[i].y)),
                                 fmaxf(fabsf(v[i].z), fabsf(v[i].w))));
    }
    __shared__ float red[8];
#pragma unroll
    for (int o = 16; o > 0; o >>= 1)
        amax = fmaxf(amax, __shfl_xor_sync(0xffffffffu, amax, o));
    if ((threadIdx.x & 31) == 0) red[threadIdx.x >> 5] = amax;
    __syncthreads();
    float m = red[0];
#pragma unroll
    for (int w = 1; w < 8; w++) m = fmaxf(m, red[w]);

    const float scale = fmaxf(m, 1e-8f) / 127.0f;
    if (threadIdx.x == 0) g_xscale[t] = scale;

    int* __restrict__ outw = reinterpret_cast<int*>(g_xq + (size_t)t * D_IN);
#pragma unroll
    for (int i = 0; i < 4; i++) {
        int q0 = (int)fminf(fmaxf(rintf(v[i].x / scale), -128.0f), 127.0f);
        int q1 = (int)fminf(fmaxf(rintf(v[i].y / scale), -128.0f), 127.0f);
        int q2 = (int)fminf(fmaxf(rintf(v[i].z / scale), -128.0f), 127.0f);
        int q3 = (int)fminf(fmaxf(rintf(v[i].w / scale), -128.0f), 127.0f);
        outw[threadIdx.x + i * 256] = (q0 & 0xFF) | ((q1 & 0xFF) << 8) |
                                      ((q2 & 0xFF) << 16) | ((q3 & 0xFF) << 24);
    }
}

// ===========================================================================
// Kernel 2: HYBRID int8 GEMM — tensor pipe (mma.sync) + ALU pipe (dp4a),
// coupled (R6 structure: shared A tile, shared per-iter __syncthreads),
// with REBALANCED columns: measured effective rates are tensor ~280 and
// dp4a ~206 MACs/cyc/SM, so tensor gets 144 cols (warp tile 32x72, 9
// n-tiles) and dp4a gets 112 cols (8x7 micro-tiles). Per-iter time drops
// from max(3.7k,5.1k)=5.1k to max(4.2k,4.45k)=4.45k cycles.
// ===========================================================================
#define BM 128
#define BN_T 144
#define BN_D 112
#define BN (BN_T + BN_D)         // 256
#define BK 64
#define STAGES 3
#define NKB (D_IN / BK)          // 64
#define ROW_B 80                 // padded row stride (tensor tiles)
#define A_TILE (BM * ROW_B)      // 10240
#define BT_TILE (BN_T * ROW_B)   // 11520
#define STAGE_T (A_TILE + BT_TILE)           // 21760
#define OFF_B2 (STAGES * STAGE_T)            // 65280
#define B2_TILE (4 * BN_D * 16)              // 7168 ([kw4][col] int4)
#define SMEM_TOTAL (OFF_B2 + STAGES * B2_TILE)   // 86784

__global__ __launch_bounds__(512, 1) void gemm_hybrid_kernel(
    const float* __restrict__ wscale,
    const float* __restrict__ bias,
    float* __restrict__ out)
{
    extern __shared__ char smem[];
    const uint32_t sbase = smem_u32(smem);

    const int tid  = threadIdx.x;
    const int lane = tid & 31;
    const int wid  = tid >> 5;

    const int m0 = blockIdx.y * BM;
    const int n0 = blockIdx.x * BN;

    if (wid < 8) {
        // ===============================================================
        // TENSOR PATH (warps 0-7): cols [n0, n0+144), mma.sync m16n8k32
        // Warp tile 32x72 = 2(M) x 9(N) mma tiles.
        // ===============================================================
        const int g  = lane >> 2;
        const int tq = lane & 3;
        const int wm = wid & 3;
        const int wn = wid >> 2;

        int acc[2][9][4];
#pragma unroll
        for (int mt = 0; mt < 2; mt++)
#pragma unroll
            for (int nt = 0; nt < 9; nt++)
#pragma unroll
                for (int r = 0; r < 4; r++) acc[mt][nt][r] = 0;

        // loader: A 512 chunks + B 576 chunks = 1088 per stage, 256 threads
        auto load_stage = [&](int s, int kb) {
            const uint32_t sa = sbase + s * STAGE_T;
            const uint32_t sb = sa + A_TILE;
            const size_t kcol = (size_t)kb * BK;
#pragma unroll
            for (int c = 0; c < 5; c++) {
                const int idx = tid + c * 256;
                if (idx < 512) {                 // A: 128 rows x 4 chunks
                    const int row = idx >> 2, kw = idx & 3;
                    CP_ASYNC16(sa + row * ROW_B + kw * 16,
                               g_xq + (size_t)(m0 + row) * D_IN + kcol + kw * 16);
                } else if (idx < 1088) {         // B: 144 rows x 4 chunks
                    const int i2 = idx - 512;
                    const int row = i2 >> 2, kw = i2 & 3;
                    CP_ASYNC16(sb + row * ROW_B + kw * 16,
                               g_wq + (size_t)(n0 + row) * D_IN + kcol + kw * 16);
                }
            }
        };

#pragma unroll
        for (int s = 0; s < STAGES - 1; s++) {
            load_stage(s, s);
            CP_COMMIT();
        }

        // A x4 addresses (per mt, ks)
        const int a_row = wm * 32 + (lane & 7) + ((lane >> 3) & 1) * 8;
        const int a_b16 = (lane >> 4) * 16;
        uint32_t a_lo[2][2];
#pragma unroll
        for (int mt = 0; mt < 2; mt++)
#pragma unroll
            for (int ks = 0; ks < 2; ks++)
                a_lo[mt][ks] = (uint32_t)((a_row + mt * 16) * ROW_B + ks * 32 + a_b16);

        // B x4 addresses (tile pairs 0..3 -> n-tiles 0..7)
        const int b_row = wn * 72 + (lane & 7) + ((lane >> 4) & 1) * 8;
        const int b_b16 = ((lane >> 3) & 1) * 16;
        uint32_t b_lo[4][2];
#pragma unroll
        for (int t = 0; t < 4; t++)
#pragma unroll
            for (int ks = 0; ks < 2; ks++)
                b_lo[t][ks] = (uint32_t)(A_TILE + (b_row + t * 16) * ROW_B + ks * 32 + b_b16);

        // B x2 address for n-tile 8 (rows wn*72+64..71); lanes 0-15 used.
        const int b2_row = wn * 72 + 64 + (lane & 7);
        uint32_t b_lo2[2];
#pragma unroll
        for (int ks = 0; ks < 2; ks++)
            b_lo2[ks] = (uint32_t)(A_TILE + b2_row * ROW_B + ks * 32 + b_b16);

#pragma unroll 1
        for (int kb = 0; kb < NKB; kb++) {
            CP_WAIT(STAGES - 2);
            __syncthreads();   // shared with dp4a warps (matched counts)

            const int pf = kb + STAGES - 1;
            if (pf < NKB) load_stage(pf % STAGES, pf);
            CP_COMMIT();

            const uint32_t st = sbase + (kb % STAGES) * STAGE_T;
#pragma unroll
            for (int ks = 0; ks < 2; ks++) {
                uint32_t af[2][4], bf[9][2];
#pragma unroll
                for (int mt = 0; mt < 2; mt++)
                    LDMATRIX_X4(af[mt][0], af[mt][1], af[mt][2], af[mt][3],
                                st + a_lo[mt][ks]);
#pragma unroll
                for (int t = 0; t < 4; t++)
                    LDMATRIX_X4(bf[2 * t][0], bf[2 * t][1], bf[2 * t + 1][0],
                                bf[2 * t + 1][1], st + b_lo[t][ks]);
                LDMATRIX_X2(bf[8][0], bf[8][1], st + b_lo2[ks]);
#pragma unroll
                for (int mt = 0; mt < 2; mt++)
#pragma unroll
                    for (int nt = 0; nt < 9; nt++)
                        mma_i8(acc[mt][nt], af[mt], bf[nt]);
            }
        }

        CP_WAIT_ALL();
        __syncthreads();
        // stage wscale/bias for the whole CTA (overlays stage 0)
        float* ws_s = reinterpret_cast<float*>(smem);
        float* bs_s = ws_s + BN;
        if (tid < BN) {
            ws_s[tid] = wscale[n0 + tid];
            bs_s[tid] = bias[n0 + tid];
        }
        __syncthreads();

        // tensor epilogue: cols n0 + wn*72 + nt*8 + tq*2
#pragma unroll
        for (int mt = 0; mt < 2; mt++) {
            const int row0 = m0 + wm * 32 + mt * 16 + g;
            const float xs0 = g_xscale[row0];
            const float xs1 = g_xscale[row0 + 8];
            float* __restrict__ o0 = out + (size_t)row0 * D_OUT;
            float* __restrict__ o1 = out + (size_t)(row0 + 8) * D_OUT;
#pragma unroll
            for (int nt = 0; nt < 9; nt++) {
                const int nl = wn * 72 + nt * 8 + tq * 2;
                const float w0 = ws_s[nl], w1 = ws_s[nl + 1];
                const float b0 = bs_s[nl], b1 = bs_s[nl + 1];
                float2 v0, v1;
                v0.x = (float)acc[mt][nt][0] * xs0 * w0 + b0;
                v0.y = (float)acc[mt][nt][1] * xs0 * w1 + b1;
                v1.x = (float)acc[mt][nt][2] * xs1 * w0 + b0;
                v1.y = (float)acc[mt][nt][3] * xs1 * w1 + b1;
                *reinterpret_cast<float2*>(o0 + n0 + nl) = v0;
                *reinterpret_cast<float2*>(o1 + n0 + nl) = v1;
            }
        }
    } else {
        // ===============================================================
        // DP4A PATH (warps 8-15): cols [n0+144, n0+256) (112 cols),
        // reading the SHARED tensor A tile (80B rows, broadcast).
        // B2 tile: [kw4][112 cols] int4 — conflict-free LDS.128.
        // ===============================================================
        const int t2 = tid - 256;         // 0..255
        const int tx = t2 & 15;           // col within group
        const int ty = t2 >> 4;           // row group 0..15

        int acc[8][7];
#pragma unroll
        for (int i = 0; i < 8; i++)
#pragma unroll
            for (int j = 0; j < 7; j++) acc[i][j] = 0;

        // loader: B2 448 chunks per stage, 256 threads
        auto load_stage_d = [&](int s, int kb) {
            const uint32_t b2 = sbase + OFF_B2 + s * B2_TILE;
            const size_t kcol = (size_t)kb * BK;
#pragma unroll
            for (int c = 0; c < 2; c++) {
                const int idx = t2 + c * 256;
                if (idx < 448) {
                    const int col = idx >> 2, kw4 = idx & 3;
                    CP_ASYNC16(b2 + (kw4 * BN_D + col) * 16,
                               g_wq + (size_t)(n0 + BN_T + col) * D_IN + kcol + kw4 * 16);
                }
            }
        };

#pragma unroll
        for (int s = 0; s < STAGES - 1; s++) {
            load_stage_d(s, s);
            CP_COMMIT();
        }

#pragma unroll 1
        for (int kb = 0; kb < NKB; kb++) {
            CP_WAIT(STAGES - 2);
            __syncthreads();   // shared with tensor warps

            const int pf = kb + STAGES - 1;
            if (pf < NKB) load_stage_d(pf % STAGES, pf);
            CP_COMMIT();

            const int s = kb % STAGES;
            const uint32_t a_t = sbase + s * STAGE_T;            // shared A
            const uint32_t b2 = sbase + OFF_B2 + s * B2_TILE;

#pragma unroll
            for (int kw4 = 0; kw4 < 4; kw4++) {
                int4 b[7];
#pragma unroll
                for (int j = 0; j < 7; j++)
                    lds128(b[j], b2 + (kw4 * BN_D + j * 16 + tx) * 16);
#pragma unroll
                for (int i = 0; i < 8; i++) {
                    int4 a;
                    lds128(a, a_t + (ty * 8 + i) * ROW_B + kw4 * 16);
#pragma unroll
                    for (int j = 0; j < 7; j++) {
                        acc[i][j] = __dp4a(a.x, b[j].x, acc[i][j]);
                        acc[i][j] = __dp4a(a.y, b[j].y, acc[i][j]);
                        acc[i][j] = __dp4a(a.z, b[j].z, acc[i][j]);
                        acc[i][j] = __dp4a(a.w, b[j].w, acc[i][j]);
                    }
                }
            }
        }

        CP_WAIT_ALL();
        __syncthreads();
        // (ws/bs staged by tensor-path threads)
        __syncthreads();

        const float* ws_s = reinterpret_cast<const float*>(smem);
        const float* bs_s = ws_s + BN;
#pragma unroll
        for (int i = 0; i < 8; i++) {
            const int m = m0 + ty * 8 + i;
            const float xs = g_xscale[m];
            float* __restrict__ orow = out + (size_t)m * D_OUT;
#pragma unroll
            for (int j = 0; j < 7; j++) {
                const int nl = BN_T + j * 16 + tx;
                orow[n0 + nl] = (float)acc[i][j] * xs * ws_s[nl] + bs_s[nl];
            }
        }
    }
}

// ===========================================================================
extern "C" void kernel_launch(void* const* d_in, const int* in_sizes, int n_in,
                              void* d_out, int out_size)
{
    const float* x      = (const float*)d_in[0];
    const int*   w32    = (const int*)d_in[1];
    const float* wscale = (const float*)d_in[2];
    const float* bias   = (const float*)d_in[3];
    float*       out    = (float*)d_out;

    const int T = in_sizes[0] / D_IN;   // 8192

    const size_t nwords = (size_t)D_OUT * D_IN / 4;
    pack_w_kernel<<<(int)((nwords + 255) / 256), 256>>>(w32);
    quant_kernel<<<T, 256>>>(x);

    static bool attr_set = false;
    if (!attr_set) {
        cudaFuncSetAttribute(gemm_hybrid_kernel,
                             cudaFuncAttributeMaxDynamicSharedMemorySize, SMEM_TOTAL);
        attr_set = true;
    }
    dim3 grid(D_OUT / BN, T / BM);      // (16, 64)
    gemm_hybrid_kernel<<<grid, 512, SMEM_TOTAL>>>(wscale, bias, out);
}

// round 10
// speedup vs baseline: 1.1384x; 1.0213x over previous
#include <cuda_runtime.h>
#include <cstdint>

// Shapes fixed by setup_inputs: x [4,2048,4096] f32, W [4096,4096] int8
// (delivered by harness as int32), wscale [4096] f32, bias [4096] f32.
#define D_IN  4096
#define D_OUT 4096
#define MAX_T 8192

// Scratch (allocation-free rule: __device__ globals)
__device__ int8_t g_xq[(size_t)MAX_T * D_IN];
__device__ float  g_xscale[MAX_T];
__device__ int8_t g_wq[(size_t)D_OUT * D_IN];

// ===========================================================================
// Helpers
// ===========================================================================
__device__ __forceinline__ uint32_t smem_u32(const void* p) {
    uint32_t a;
    asm("{ .reg .u64 t; cvta.to.shared.u64 t, %1; cvt.u32.u64 %0, t; }"
        : "=r"(a) : "l"(p));
    return a;
}
#define CP_ASYNC16(dst, src) \
    asm volatile("cp.async.cg.shared.global [%0], [%1], 16;" \
                 :: "r"(dst), "l"(src) : "memory")
#define CP_COMMIT() asm volatile("cp.async.commit_group;" ::: "memory")
#define CP_WAIT(n)  asm volatile("cp.async.wait_group %0;" :: "n"(n) : "memory")
#define CP_WAIT_ALL() asm volatile("cp.async.wait_all;" ::: "memory")

#define LDMATRIX_X4(r0, r1, r2, r3, addr)                                     \
    asm volatile("ldmatrix.sync.aligned.m8n8.x4.shared.b16 {%0,%1,%2,%3}, [%4];" \
                 : "=r"(r0), "=r"(r1), "=r"(r2), "=r"(r3) : "r"(addr))
#define LDMATRIX_X2(r0, r1, addr)                                             \
    asm volatile("ldmatrix.sync.aligned.m8n8.x2.shared.b16 {%0,%1}, [%2];"    \
                 : "=r"(r0), "=r"(r1) : "r"(addr))

__device__ __forceinline__ void lds128(int4& v, uint32_t addr) {
    asm volatile("ld.shared.v4.b32 {%0,%1,%2,%3}, [%4];"
                 : "=r"(v.x), "=r"(v.y), "=r"(v.z), "=r"(v.w) : "r"(addr));
}

// int8 tensor-core MMA (sm_80 baseline)
__device__ __forceinline__ void mma_i8(int* c, const uint32_t* a, const uint32_t* b) {
    asm volatile(
        "mma.sync.aligned.m16n8k32.row.col.s32.s8.s8.s32 "
        "{%0,%1,%2,%3}, {%4,%5,%6,%7}, {%8,%9}, {%0,%1,%2,%3};"
        : "+r"(c[0]), "+r"(c[1]), "+r"(c[2]), "+r"(c[3])
        : "r"(a[0]), "r"(a[1]), "r"(a[2]), "r"(a[3]), "r"(b[0]), "r"(b[1]));
}

// ===========================================================================
// Kernel 0: repack weights int32 -> int8
// ===========================================================================
__global__ __launch_bounds__(256) void pack_w_kernel(const int* __restrict__ w32)
{
    const size_t i = (size_t)blockIdx.x * blockDim.x + threadIdx.x;
    const size_t nwords = (size_t)D_OUT * D_IN / 4;
    if (i >= nwords) return;
    const int4 v = reinterpret_cast<const int4*>(w32)[i];
    reinterpret_cast<int*>(g_wq)[i] =
        (v.x & 0xFF) | ((v.y & 0xFF) << 8) | ((v.z & 0xFF) << 16) | ((v.w & 0xFF) << 24);
}

// ===========================================================================
// Kernel 1: dynamic per-token int8 quantization (one CTA / token)
// ===========================================================================
__global__ __launch_bounds__(256) void quant_kernel(const float* __restrict__ x)
{
    const int t = blockIdx.x;
    const float4* __restrict__ xr = reinterpret_cast<const float4*>(x + (size_t)t * D_IN);

    float4 v[4];
    float amax = 0.0f;
#pragma unroll
    for (int i = 0; i < 4; i++) {
        v[i] = xr[threadIdx.x + i * 256];
        amax = fmaxf(amax, fmaxf(fmaxf(fabsf(v[i].x), fabsf(v[i].y)),
                                 fmaxf(fabsf(v[i].z), fabsf(v[i].w))));
    }
    __shared__ float red[8];
#pragma unroll
    for (int o = 16; o > 0; o >>= 1)
        amax = fmaxf(amax, __shfl_xor_sync(0xffffffffu, amax, o));
    if ((threadIdx.x & 31) == 0) red[threadIdx.x >> 5] = amax;
    __syncthreads();
    float m = red[0];
#pragma unroll
    for (int w = 1; w < 8; w++) m = fmaxf(m, red[w]);

    const float scale = fmaxf(m, 1e-8f) / 127.0f;
    if (threadIdx.x == 0) g_xscale[t] = scale;

    int* __restrict__ outw = reinterpret_cast<int*>(g_xq + (size_t)t * D_IN);
#pragma unroll
    for (int i = 0; i < 4; i++) {
        int q0 = (int)fminf(fmaxf(rintf(v[i].x / scale), -128.0f), 127.0f);
        int q1 = (int)fminf(fmaxf(rintf(v[i].y / scale), -128.0f), 127.0f);
        int q2 = (int)fminf(fmaxf(rintf(v[i].z / scale), -128.0f), 127.0f);
        int q3 = (int)fminf(fmaxf(rintf(v[i].w / scale), -128.0f), 127.0f);
        outw[threadIdx.x + i * 256] = (q0 & 0xFF) | ((q1 & 0xFF) << 8) |
                                      ((q2 & 0xFF) << 16) | ((q3 & 0xFF) << 24);
    }
}

// ===========================================================================
// Kernel 2: HYBRID int8 GEMM — tensor pipe (mma.sync, 144 cols) + ALU pipe
// (dp4a, 112 cols), coupled via one shared barrier per K-iter. R10 change:
// BK 64 -> 128 (NKB 32), halving barrier/wait/loader fixed costs per unit
// of K (measured ~1.0k cyc/iter overhead at BK=64). Row stride 144B keeps
// ldmatrix conflict-free (bank(row g) = 4g mod 32, distinct for g=0..7).
// ===========================================================================
#define BM 128
#define BN_T 144
#define BN_D 112
#define BN (BN_T + BN_D)         // 256
#define BK 128
#define STAGES 3
#define NKB (D_IN / BK)          // 32
#define ROW_B 144                // 128B data + 16B pad
#define A_TILE (BM * ROW_B)      // 18432
#define BT_TILE (BN_T * ROW_B)   // 20736
#define STAGE_T (A_TILE + BT_TILE)           // 39168
#define OFF_B2 (STAGES * STAGE_T)            // 117504
#define B2_TILE (8 * BN_D * 16)              // 14336 ([kw8][col] int4)
#define SMEM_TOTAL (OFF_B2 + STAGES * B2_TILE)   // 160512

__global__ __launch_bounds__(512, 1) void gemm_hybrid_kernel(
    const float* __restrict__ wscale,
    const float* __restrict__ bias,
    float* __restrict__ out)
{
    extern __shared__ char smem[];
    const uint32_t sbase = smem_u32(smem);

    const int tid  = threadIdx.x;
    const int lane = tid & 31;
    const int wid  = tid >> 5;

    const int m0 = blockIdx.y * BM;
    const int n0 = blockIdx.x * BN;

    if (wid < 8) {
        // ===============================================================
        // TENSOR PATH (warps 0-7): cols [n0, n0+144), warp tile 32x72
        // (2 M-tiles x 9 N-tiles), 4 K=32 steps per BK=128 stage.
        // ===============================================================
        const int g  = lane >> 2;
        const int tq = lane & 3;
        const int wm = wid & 3;
        const int wn = wid >> 2;

        int acc[2][9][4];
#pragma unroll
        for (int mt = 0; mt < 2; mt++)
#pragma unroll
            for (int nt = 0; nt < 9; nt++)
#pragma unroll
                for (int r = 0; r < 4; r++) acc[mt][nt][r] = 0;

        // loader: A 1024 + B 1152 = 2176 16B-chunks per stage, 256 threads
        auto load_stage = [&](int s, int kb) {
            const uint32_t sa = sbase + s * STAGE_T;
            const uint32_t sb = sa + A_TILE;
            const size_t kcol = (size_t)kb * BK;
#pragma unroll
            for (int c = 0; c < 9; c++) {
                const int idx = tid + c * 256;
                if (idx < 1024) {                // A: 128 rows x 8 chunks
                    const int row = idx >> 3, kw = idx & 7;
                    CP_ASYNC16(sa + row * ROW_B + kw * 16,
                               g_xq + (size_t)(m0 + row) * D_IN + kcol + kw * 16);
                } else if (idx < 2176) {         // B: 144 rows x 8 chunks
                    const int i2 = idx - 1024;
                    const int row = i2 >> 3, kw = i2 & 7;
                    CP_ASYNC16(sb + row * ROW_B + kw * 16,
                               g_wq + (size_t)(n0 + row) * D_IN + kcol + kw * 16);
                }
            }
        };

#pragma unroll
        for (int s = 0; s < STAGES - 1; s++) {
            load_stage(s, s);
            CP_COMMIT();
        }

        // A x4 addresses (per mt; +ks*32 at use)
        const int a_row = wm * 32 + (lane & 7) + ((lane >> 3) & 1) * 8;
        const int a_b16 = (lane >> 4) * 16;
        uint32_t a_lo[2];
#pragma unroll
        for (int mt = 0; mt < 2; mt++)
            a_lo[mt] = (uint32_t)((a_row + mt * 16) * ROW_B + a_b16);

        // B x4 addresses (tile pairs 0..3 -> n-tiles 0..7)
        const int b_row = wn * 72 + (lane & 7) + ((lane >> 4) & 1) * 8;
        const int b_b16 = ((lane >> 3) & 1) * 16;
        uint32_t b_lo[4];
#pragma unroll
        for (int t = 0; t < 4; t++)
            b_lo[t] = (uint32_t)(A_TILE + (b_row + t * 16) * ROW_B + b_b16);

        // B x2 address for n-tile 8
        const int b2_row = wn * 72 + 64 + (lane & 7);
        const uint32_t b_lo2 = (uint32_t)(A_TILE + b2_row * ROW_B + b_b16);

#pragma unroll 1
        for (int kb = 0; kb < NKB; kb++) {
            CP_WAIT(STAGES - 2);
            __syncthreads();   // shared with dp4a warps (matched counts)

            const int pf = kb + STAGES - 1;
            if (pf < NKB) load_stage(pf % STAGES, pf);
            CP_COMMIT();

            const uint32_t st = sbase + (kb % STAGES) * STAGE_T;
#pragma unroll
            for (int ks = 0; ks < 4; ks++) {     // 4 x K=32 per BK=128
                const uint32_t ko = ks * 32;
                uint32_t af[2][4], bf[9][2];
#pragma unroll
                for (int mt = 0; mt < 2; mt++)
                    LDMATRIX_X4(af[mt][0], af[mt][1], af[mt][2], af[mt][3],
                                st + a_lo[mt] + ko);
#pragma unroll
                for (int t = 0; t < 4; t++)
                    LDMATRIX_X4(bf[2 * t][0], bf[2 * t][1], bf[2 * t + 1][0],
                                bf[2 * t + 1][1], st + b_lo[t] + ko);
                LDMATRIX_X2(bf[8][0], bf[8][1], st + b_lo2 + ko);
#pragma unroll
                for (int mt = 0; mt < 2; mt++)
#pragma unroll
                    for (int nt = 0; nt < 9; nt++)
                        mma_i8(acc[mt][nt], af[mt], bf[nt]);
            }
        }

        CP_WAIT_ALL();
        __syncthreads();
        // stage wscale/bias for the whole CTA (overlays stage 0)
        float* ws_s = reinterpret_cast<float*>(smem);
        float* bs_s = ws_s + BN;
        if (tid < BN) {
            ws_s[tid] = wscale[n0 + tid];
            bs_s[tid] = bias[n0 + tid];
        }
        __syncthreads();

        // tensor epilogue
#pragma unroll
        for (int mt = 0; mt < 2; mt++) {
            const int row0 = m0 + wm * 32 + mt * 16 + g;
            const float xs0 = g_xscale[row0];
            const float xs1 = g_xscale[row0 + 8];
            float* __restrict__ o0 = out + (size_t)row0 * D_OUT;
            float* __restrict__ o1 = out + (size_t)(row0 + 8) * D_OUT;
#pragma unroll
            for (int nt = 0; nt < 9; nt++) {
                const int nl = wn * 72 + nt * 8 + tq * 2;
                const float w0 = ws_s[nl], w1 = ws_s[nl + 1];
                const float b0 = bs_s[nl], b1 = bs_s[nl + 1];
                float2 v0, v1;
                v0.x = (float)acc[mt][nt][0] * xs0 * w0 + b0;
                v0.y = (float)acc[mt][nt][1] * xs0 * w1 + b1;
                v1.x = (float)acc[mt][nt][2] * xs1 * w0 + b0;
                v1.y = (float)acc[mt][nt][3] * xs1 * w1 + b1;
                *reinterpret_cast<float2*>(o0 + n0 + nl) = v0;
                *reinterpret_cast<float2*>(o1 + n0 + nl) = v1;
            }
        }
    } else {
        // ===============================================================
        // DP4A PATH (warps 8-15): cols [n0+144, n0+256) (112 cols),
        // reading the SHARED tensor A tile (144B rows, broadcast).
        // B2 tile: [kw8][112 cols] int4 — conflict-free LDS.128.
        // ===============================================================
        const int t2 = tid - 256;         // 0..255
        const int tx = t2 & 15;           // col within group
        const int ty = t2 >> 4;           // row group 0..15

        int acc[8][7];
#pragma unroll
        for (int i = 0; i < 8; i++)
#pragma unroll
            for (int j = 0; j < 7; j++) acc[i][j] = 0;

        // loader: B2 896 chunks per stage, 256 threads
        auto load_stage_d = [&](int s, int kb) {
            const uint32_t b2 = sbase + OFF_B2 + s * B2_TILE;
            const size_t kcol = (size_t)kb * BK;
#pragma unroll
            for (int c = 0; c < 4; c++) {
                const int idx = t2 + c * 256;
                if (idx < 896) {
                    const int col = idx >> 3, kw = idx & 7;
                    CP_ASYNC16(b2 + (kw * BN_D + col) * 16,
                               g_wq + (size_t)(n0 + BN_T + col) * D_IN + kcol + kw * 16);
                }
            }
        };

#pragma unroll
        for (int s = 0; s < STAGES - 1; s++) {
            load_stage_d(s, s);
            CP_COMMIT();
        }

#pragma unroll 1
        for (int kb = 0; kb < NKB; kb++) {
            CP_WAIT(STAGES - 2);
            __syncthreads();   // shared with tensor warps

            const int pf = kb + STAGES - 1;
            if (pf < NKB) load_stage_d(pf % STAGES, pf);
            CP_COMMIT();

            const int s = kb % STAGES;
            const uint32_t a_t = sbase + s * STAGE_T;            // shared A
            const uint32_t b2 = sbase + OFF_B2 + s * B2_TILE;

#pragma unroll
            for (int kw = 0; kw < 8; kw++) {     // 8 x K=16B per BK=128
                int4 b[7];
#pragma unroll
                for (int j = 0; j < 7; j++)
                    lds128(b[j], b2 + (kw * BN_D + j * 16 + tx) * 16);
#pragma unroll
                for (int i = 0; i < 8; i++) {
                    int4 a;
                    lds128(a, a_t + (ty * 8 + i) * ROW_B + kw * 16);
#pragma unroll
                    for (int j = 0; j < 7; j++) {
                        acc[i][j] = __dp4a(a.x, b[j].x, acc[i][j]);
                        acc[i][j] = __dp4a(a.y, b[j].y, acc[i][j]);
                        acc[i][j] = __dp4a(a.z, b[j].z, acc[i][j]);
                        acc[i][j] = __dp4a(a.w, b[j].w, acc[i][j]);
                    }
                }
            }
        }

        CP_WAIT_ALL();
        __syncthreads();
        // (ws/bs staged by tensor-path threads)
        __syncthreads();

        const float* ws_s = reinterpret_cast<const float*>(smem);
        const float* bs_s = ws_s + BN;
#pragma unroll
        for (int i = 0; i < 8; i++) {
            const int m = m0 + ty * 8 + i;
            const float xs = g_xscale[m];
            float* __restrict__ orow = out + (size_t)m * D_OUT;
#pragma unroll
            for (int j = 0; j < 7; j++) {
                const int nl = BN_T + j * 16 + tx;
                orow[n0 + nl] = (float)acc[i][j] * xs * ws_s[nl] + bs_s[nl];
            }
        }
    }
}

// ===========================================================================
extern "C" void kernel_launch(void* const* d_in, const int* in_sizes, int n_in,
                              void* d_out, int out_size)
{
    const float* x      = (const float*)d_in[0];
    const int*   w32    = (const int*)d_in[1];
    const float* wscale = (const float*)d_in[2];
    const float* bias   = (const float*)d_in[3];
    float*       out    = (float*)d_out;

    const int T = in_sizes[0] / D_IN;   // 8192

    const size_t nwords = (size_t)D_OUT * D_IN / 4;
    pack_w_kernel<<<(int)((nwords + 255) / 256), 256>>>(w32);
    quant_kernel<<<T, 256>>>(x);

    static bool attr_set = false;
    if (!attr_set) {
        cudaFuncSetAttribute(gemm_hybrid_kernel,
                             cudaFuncAttributeMaxDynamicSharedMemorySize, SMEM_TOTAL);
        attr_set = true;
    }
    dim3 grid(D_OUT / BN, T / BM);      // (16, 64)
    gemm_hybrid_kernel<<<grid, 512, SMEM_TOTAL>>>(wscale, bias, out);
}